// round 6
// baseline (speedup 1.0000x reference)
#include <cuda_runtime.h>
#include <cuda_bf16.h>
#include <stdint.h>

// ---------------------------------------------------------------------------
// AnnularPatchEmbed — disjoint ring masks -> segmented GEMM over ring-sorted
// pixel list. R6: cp.async double-buffered GEMM mainloop (hide gather
// latency), smem-staged parallel scan.
// ---------------------------------------------------------------------------

#define IMG      224
#define P        (IMG * IMG)       // 50176
#define B        64
#define NRINGS   16
#define TOKD     256
#define OUTD     192
#define NTILES   (P / 256)         // 196
#define KC       192               // K-chunk per GEMM block
#define KB       32                // K step inside GEMM block
#define MAXCHUNK 288
#define APAD     68                // As row stride (floats), 272B (16B-aligned)
#define BPAD     132               // Bs row stride (floats), 528B (16B-aligned)

// dynamic smem layout (bytes): idxS[KC] | As[2][KB][APAD] | Bs[2][KB][BPAD]
#define SMEM_BYTES (KC * 4 + 2 * KB * APAD * 4 + 2 * KB * BPAD * 4)  // 51968

typedef unsigned long long ull;

#define FMA_F32X2(d, a, b, c) \
    asm("fma.rn.f32x2 %0, %1, %2, %3;" : "=l"(d) : "l"(a), "l"(b), "l"(c))
#define PACK_F32X2(out, lo, hi) \
    asm("mov.b64 %0, {%1, %2};" : "=l"(out) : "f"(lo), "f"(hi))
#define UNPACK_F32X2(lo, hi, in) \
    asm("mov.b64 {%0, %1}, %2;" : "=f"(lo), "=f"(hi) : "l"(in))

__device__ __forceinline__ void cp4(uint32_t dst, const void* src) {
    asm volatile("cp.async.ca.shared.global [%0], [%1], 4;" :: "r"(dst), "l"(src));
}
#define CP_COMMIT() asm volatile("cp.async.commit_group;" ::: "memory")
#define CP_WAIT1()  asm volatile("cp.async.wait_group 1;" ::: "memory")
#define CP_WAIT0()  asm volatile("cp.async.wait_group 0;" ::: "memory")

// ---------------- device scratch (no allocations allowed) -----------------
__device__ unsigned char g_rid[P];
__device__ int   g_tileCnt[NTILES * NRINGS];
__device__ int   g_tileOff[NTILES * NRINGS];
__device__ int   g_ringBase[NRINGS + 1];
__device__ int   g_idx[P];
__device__ int   g_chunkRing[MAXCHUNK];
__device__ int   g_chunkK0[MAXCHUNK];
__device__ int   g_chunkLen[MAXCHUNK];
__device__ int   g_nChunks;
__device__ float4 g_tokens4[(B * NRINGS * TOKD) / 4];   // 1 MB
__device__ float  g_fcwT[TOKD * OUTD];
__device__ float  g_zeroF[8] = {0, 0, 0, 0, 0, 0, 0, 0};

// ---------------------------------------------------------------------------
// 0) fused prep: [0,256) zero tokens | [256,304) transpose fc_w | [304,500) rid
// ---------------------------------------------------------------------------
__global__ void k_prep(const float* __restrict__ fc_w,
                       const float* __restrict__ masks) {
    int blk = blockIdx.x, t = threadIdx.x;

    if (blk < 256) {
        g_tokens4[blk * 256 + t] = make_float4(0.f, 0.f, 0.f, 0.f);
        return;
    }
    if (blk < 304) {
        int idx = (blk - 256) * 256 + t;
        if (idx < OUTD * TOKD / 4) {
            int o = idx / (TOKD / 4), d4 = idx % (TOKD / 4);
            float4 v = ((const float4*)fc_w)[idx];
            g_fcwT[(d4 * 4 + 0) * OUTD + o] = v.x;
            g_fcwT[(d4 * 4 + 1) * OUTD + o] = v.y;
            g_fcwT[(d4 * 4 + 2) * OUTD + o] = v.z;
            g_fcwT[(d4 * 4 + 3) * OUTD + o] = v.w;
        }
        return;
    }
    __shared__ int hist[NRINGS];
    int tile = blk - 304;
    if (t < NRINGS) hist[t] = 0;
    __syncthreads();
    int p = tile * 256 + t;
    int r = 255;
#pragma unroll
    for (int c = 0; c < NRINGS; c++)
        if (masks[c * P + p] > 0.5f) r = c;
    g_rid[p] = (unsigned char)r;
    if (r < NRINGS) atomicAdd(&hist[r], 1);
    __syncthreads();
    if (t < NRINGS) g_tileCnt[tile * NRINGS + t] = hist[t];
}

// ---------------------------------------------------------------------------
// 1) parallel scans + chunk build; counts staged to smem in one coalesced burst
// ---------------------------------------------------------------------------
__global__ void k_scan_chunks() {
    __shared__ int sCnt[NRINGS][NTILES + 4];   // [ring][tile], 12.8 KB
    __shared__ int ringTot[NRINGS];
    __shared__ int ringBaseS[NRINGS];
    __shared__ int chunkBaseS[NRINGS];
    int t = threadIdx.x, w = t >> 5, lane = t & 31;

    for (int j = t; j < NTILES * NRINGS; j += 512)
        sCnt[j & (NRINGS - 1)][j >> 4] = g_tileCnt[j];   // j = tile*16 + ring
    __syncthreads();

    if (w < NRINGS) {
        int run = 0;
        for (int base = 0; base < NTILES; base += 32) {
            int i = base + lane;
            int v = (i < NTILES) ? sCnt[w][i] : 0;
            int s = v;
#pragma unroll
            for (int d = 1; d < 32; d <<= 1) {
                int n = __shfl_up_sync(0xffffffffu, s, d);
                if (lane >= d) s += n;
            }
            if (i < NTILES) g_tileOff[i * NRINGS + w] = run + s - v;
            run += __shfl_sync(0xffffffffu, s, 31);
        }
        if (lane == 0) ringTot[w] = run;
    }
    __syncthreads();

    if (w == 0) {
        int v = (lane < NRINGS) ? ringTot[lane] : 0;
        int s = v;
#pragma unroll
        for (int d = 1; d < 32; d <<= 1) {
            int n = __shfl_up_sync(0xffffffffu, s, d);
            if (lane >= d) s += n;
        }
        if (lane < NRINGS) { ringBaseS[lane] = s - v; g_ringBase[lane] = s - v; }
        if (lane == NRINGS - 1) g_ringBase[NRINGS] = s;

        int nc = (v + KC - 1) / KC;
        int cs = nc;
#pragma unroll
        for (int d = 1; d < 32; d <<= 1) {
            int n = __shfl_up_sync(0xffffffffu, cs, d);
            if (lane >= d) cs += n;
        }
        if (lane < NRINGS) chunkBaseS[lane] = cs - nc;
        if (lane == NRINGS - 1) g_nChunks = cs;
    }
    __syncthreads();

    if (w < NRINGS) {
        int tot = ringTot[w];
        int nc  = (tot + KC - 1) / KC;
        if (lane < nc) {
            int g = chunkBaseS[w] + lane;
            int k0 = lane * KC;
            g_chunkRing[g] = w;
            g_chunkK0[g]   = ringBaseS[w] + k0;
            g_chunkLen[g]  = min(KC, tot - k0);
        }
    }
}

// ---------------------------------------------------------------------------
// 2) single-pass stable ring-sorted compaction
// ---------------------------------------------------------------------------
__global__ void k_scatter() {
    __shared__ int wcnt[8][NRINGS];
    __shared__ int wpre[8][NRINGS];
    int t = threadIdx.x, tile = blockIdx.x;
    int lane = t & 31, w = t >> 5;

    if (t < 8 * NRINGS) ((int*)wcnt)[t] = 0;
    __syncthreads();

    int p = tile * 256 + t;
    int r = g_rid[p];
    unsigned peers = __match_any_sync(0xffffffffu, r);
    int lr = __popc(peers & ((1u << lane) - 1u));
    bool valid = (r < NRINGS);
    if (valid && lane == (__ffs(peers) - 1)) wcnt[w][r] = __popc(peers);
    __syncthreads();

    if (t < NRINGS) {
        int s = 0;
#pragma unroll
        for (int i = 0; i < 8; i++) { int v = wcnt[i][t]; wpre[i][t] = s; s += v; }
    }
    __syncthreads();

    if (valid) {
        int pos = g_ringBase[r] + g_tileOff[tile * NRINGS + r] + wpre[w][r] + lr;
        g_idx[pos] = p;
    }
}

// ---------------------------------------------------------------------------
// 3) segmented GEMM, cp.async double-buffered, f32x2 packed FMA.
//    Block=(chunk, d-half), 128 threads, 8x8 outputs/thread, M=64 x N=128.
// ---------------------------------------------------------------------------
__global__ void __launch_bounds__(128, 4)
k_gemm_tokens(const float* __restrict__ x, const float* __restrict__ W) {
    int chunk = blockIdx.x;
    if (chunk >= g_nChunks) return;
    int ring  = g_chunkRing[chunk];
    int kbeg  = g_chunkK0[chunk];
    int klen  = g_chunkLen[chunk];
    int dBase = blockIdx.y * 128;

    extern __shared__ int dynS[];
    int*   idxS = dynS;                               // [KC]
    float* Asm  = (float*)(dynS + KC);                // [2][KB][APAD]
    float* Bsm  = Asm + 2 * KB * APAD;                // [2][KB][BPAD]

    int t    = threadIdx.x;          // 0..127
    int mi   = t >> 4;               // 0..7  -> rows mi*8..+7
    int ni   = t & 15;               // 0..15 -> cols ni*8..+7
    int lane = t & 31;               // k slot this thread fills
    int w    = t >> 5;               // 0..3

    // stage chunk indices (padded with -1)
    for (int i = t; i < KC; i += 128)
        idxS[i] = (i < klen) ? g_idx[kbeg + i] : -1;
    __syncthreads();

    uint32_t aSm = (uint32_t)__cvta_generic_to_shared(Asm);
    uint32_t bSm = (uint32_t)__cvta_generic_to_shared(Bsm);

    // async fill of buffer `buf` with K-step `it`
    auto issue = [&](int it, int buf) {
        int k  = it * KB + lane;
        int pp = idxS[k];
        uint32_t aBase = aSm + (((buf * KB + lane) * APAD) + w * 16) * 4;
        uint32_t bBase = bSm + (((buf * KB + lane) * BPAD) + w * 32) * 4;
        if (pp >= 0) {
            const float* xs = x + (size_t)(w * 16) * P + pp;
#pragma unroll
            for (int i = 0; i < 16; i++) cp4(aBase + i * 4, xs + (size_t)i * P);
            const float* ws = W + (size_t)(dBase + w * 32) * P + pp;
#pragma unroll
            for (int i = 0; i < 32; i++) cp4(bBase + i * 4, ws + (size_t)i * P);
        } else {
#pragma unroll
            for (int i = 0; i < 16; i++) cp4(aBase + i * 4, g_zeroF);
#pragma unroll
            for (int i = 0; i < 32; i++) cp4(bBase + i * 4, g_zeroF);
        }
    };

    ull acc[8][4];
#pragma unroll
    for (int i = 0; i < 8; i++)
#pragma unroll
        for (int j = 0; j < 4; j++) acc[i][j] = 0ull;

    int iters = (klen + KB - 1) / KB;
    issue(0, 0);
    CP_COMMIT();

    for (int it = 0; it < iters; ++it) {
        int buf = it & 1;
        if (it + 1 < iters) {           // prefetch next while computing this
            issue(it + 1, buf ^ 1);
            CP_COMMIT();
            CP_WAIT1();
        } else {
            CP_WAIT0();
        }
        __syncthreads();

        const float* aB = Asm + (size_t)buf * KB * APAD;
        const float* bB = Bsm + (size_t)buf * KB * BPAD;
#pragma unroll
        for (int k2 = 0; k2 < KB; k2++) {
            const float* aRow = aB + k2 * APAD;
            const float* bRow = bB + k2 * BPAD;
            float4 aL = *(const float4*)(aRow + mi * 8);
            float4 aH = *(const float4*)(aRow + mi * 8 + 4);
            ulonglong2 bL = *(const ulonglong2*)(bRow + ni * 8);
            ulonglong2 bH = *(const ulonglong2*)(bRow + ni * 8 + 4);
            ull b[4] = { bL.x, bL.y, bH.x, bH.y };

            ull a2[8];
            PACK_F32X2(a2[0], aL.x, aL.x);
            PACK_F32X2(a2[1], aL.y, aL.y);
            PACK_F32X2(a2[2], aL.z, aL.z);
            PACK_F32X2(a2[3], aL.w, aL.w);
            PACK_F32X2(a2[4], aH.x, aH.x);
            PACK_F32X2(a2[5], aH.y, aH.y);
            PACK_F32X2(a2[6], aH.z, aH.z);
            PACK_F32X2(a2[7], aH.w, aH.w);

#pragma unroll
            for (int i = 0; i < 8; i++)
#pragma unroll
                for (int j = 0; j < 4; j++)
                    FMA_F32X2(acc[i][j], a2[i], b[j], acc[i][j]);
        }
        __syncthreads();
    }

    float* tokens = (float*)g_tokens4;
#pragma unroll
    for (int i = 0; i < 8; i++) {
        int bb = mi * 8 + i;
        float* dst = tokens + bb * (NRINGS * TOKD) + ring * TOKD + dBase + ni * 8;
#pragma unroll
        for (int j = 0; j < 4; j++) {
            float lo, hi;
            UNPACK_F32X2(lo, hi, acc[i][j]);
            atomicAdd(dst + 2 * j,     lo);
            atomicAdd(dst + 2 * j + 1, hi);
        }
    }
}

// ---------------------------------------------------------------------------
// 4) stage 2: out[b,c,o] = bias[o] + sum_d tokens[b,c,d] * fcwT[d,o]
// ---------------------------------------------------------------------------
__global__ void k_stage2(const float* __restrict__ fc_b, float* __restrict__ out) {
    int b   = blockIdx.x;
    int ch0 = blockIdx.y * 8;
    int o   = threadIdx.x;     // 0..191
    __shared__ float4 tok[8][64];

    const float4* src = g_tokens4 + (b * NRINGS + ch0) * (TOKD / 4);
    for (int i = o; i < 8 * 64; i += OUTD)
        tok[i >> 6][i & 63] = src[i];
    __syncthreads();

    float bias = fc_b[o];
    float acc[8];
#pragma unroll
    for (int c = 0; c < 8; c++) acc[c] = bias;

    for (int d4 = 0; d4 < 64; d4++) {
        float w0 = g_fcwT[(d4 * 4 + 0) * OUTD + o];
        float w1 = g_fcwT[(d4 * 4 + 1) * OUTD + o];
        float w2 = g_fcwT[(d4 * 4 + 2) * OUTD + o];
        float w3 = g_fcwT[(d4 * 4 + 3) * OUTD + o];
#pragma unroll
        for (int c = 0; c < 8; c++) {
            float4 tv = tok[c][d4];
            acc[c] += tv.x * w0 + tv.y * w1 + tv.z * w2 + tv.w * w3;
        }
    }
#pragma unroll
    for (int c = 0; c < 8; c++)
        out[b * (NRINGS * OUTD) + (ch0 + c) * OUTD + o] = acc[c];
}

// ---------------------------------------------------------------------------
extern "C" void kernel_launch(void* const* d_in, const int* in_sizes, int n_in,
                              void* d_out, int out_size) {
    const float *x = nullptr, *W = nullptr, *fc_w = nullptr, *fc_b = nullptr,
                *masks = nullptr;
    for (int i = 0; i < n_in; i++) {
        switch (in_sizes[i]) {
            case B * P:            x     = (const float*)d_in[i]; break;
            case TOKD * P:         W     = (const float*)d_in[i]; break;
            case OUTD * TOKD:      fc_w  = (const float*)d_in[i]; break;
            case OUTD:             fc_b  = (const float*)d_in[i]; break;
            case NRINGS * P:       masks = (const float*)d_in[i]; break;
            default: break;
        }
    }
    if (!x || !W || !fc_w || !fc_b || !masks) {
        x     = (const float*)d_in[0];
        W     = (const float*)d_in[1];
        fc_w  = (const float*)d_in[2];
        fc_b  = (const float*)d_in[3];
        masks = (const float*)d_in[4];
    }
    float* out = (float*)d_out;

    cudaFuncSetAttribute(k_gemm_tokens,
                         cudaFuncAttributeMaxDynamicSharedMemorySize, SMEM_BYTES);

    k_prep        <<<256 + 48 + NTILES, 256>>>(fc_w, masks);
    k_scan_chunks <<<1, 512>>>();
    k_scatter     <<<NTILES, 256>>>();
    k_gemm_tokens <<<dim3(MAXCHUNK, 2), 128, SMEM_BYTES>>>(x, W);
    k_stage2      <<<dim3(B, 2), OUTD>>>(fc_b, out);
}